// round 15
// baseline (speedup 1.0000x reference)
#include <cuda_runtime.h>
#include <cuda_bf16.h>
#include <math.h>

// Problem constants
#define B_  16
#define C_  4
#define J_  19
#define T_  256
#define S_  10
#define NCH (C_*J_*T_)          // 19456 BN channels
#define NPIX (B_*T_*S_)         // 40960 pixels
#define EPSV 1e-5f

#define PPB 8                   // pixels per block
#define AST 168                 // activation stride (8*l4+r4 conflict-free)
#define WST 68                  // weight stride (4*r4+l4 conflict-free)
#define NTH 320
#define LTS 28                  // LT row stride
#define LTP (J_*LTS)            // 532 per-pixel LT stride

typedef unsigned long long u64;
typedef unsigned int u32;

// ---- f32x2 packed helpers (scalar phases) --------------------------------------
__device__ __forceinline__ u64 dup2(float a) {
    u64 r; asm("mov.b64 %0, {%1, %1};" : "=l"(r) : "f"(a)); return r;
}
__device__ __forceinline__ void upk2(u64 v, float& lo, float& hi) {
    asm("mov.b64 {%0, %1}, %2;" : "=f"(lo), "=f"(hi) : "l"(v));
}
__device__ __forceinline__ void fma2(u64& d, u64 a, u64 b) {
    asm("fma.rn.f32x2 %0, %1, %2, %0;" : "+l"(d) : "l"(a), "l"(b));
}
__device__ __forceinline__ void lds_v2u64(const float* p, u64& lo, u64& hi) {
    unsigned a = (unsigned)__cvta_generic_to_shared(p);
    asm("ld.shared.v2.u64 {%0, %1}, [%2];" : "=l"(lo), "=l"(hi) : "r"(a));
}
// ---- tf32 helpers ---------------------------------------------------------------
__device__ __forceinline__ u32 f2tf(float f) {
    u32 u; asm("cvt.rna.tf32.f32 %0, %1;" : "=r"(u) : "f"(f)); return u;
}
__device__ __forceinline__ void mma_tf32(float d[4], const u32 a[4], const u32 b[2]) {
    asm volatile(
        "mma.sync.aligned.m16n8k8.row.col.f32.tf32.tf32.f32 "
        "{%0,%1,%2,%3}, {%4,%5,%6,%7}, {%8,%9}, {%0,%1,%2,%3};\n"
        : "+f"(d[0]), "+f"(d[1]), "+f"(d[2]), "+f"(d[3])
        : "r"(a[0]), "r"(a[1]), "r"(a[2]), "r"(a[3]), "r"(b[0]), "r"(b[1]));
}

// ---------------- device scratch ----------------------------------------------
__device__ float g_bn_a[NCH + 256];   // +pad so t+1 overread is safe
__device__ float g_bn_b[NCH + 256];
__device__ float g_w1t[C_*64];        // w1t[c][d] (fp32, phase B)
__device__ u32   g_w2s[64*WST];       // tf32, strided: [d*68 + k]
__device__ u32   g_Ms [64*WST];       // tf32 M[a][b] at [a*68 + b]
__device__ u32   g_Wts[64*WST];       // tf32 Wt[o][c] at [o*68 + c]
__device__ float g_v[64];

// ---------------- kernel 1: BN statistics ---------------------------------------
__global__ void bn_stats_kernel(const float* __restrict__ x,
                                const float* __restrict__ gamma,
                                const float* __restrict__ beta) {
    int ch = blockIdx.x * 8 + (threadIdx.x >> 5);
    if (ch >= NCH) return;
    int lane = threadIdx.x & 31;
    float s = 0.f, ss = 0.f;
    for (int e = lane; e < B_ * S_; e += 32) {
        int b = e / S_, si = e % S_;
        float v = x[(b * NCH + ch) * S_ + si];
        s += v; ss += v * v;
    }
    #pragma unroll
    for (int off = 16; off; off >>= 1) {
        s  += __shfl_xor_sync(0xffffffffu, s,  off);
        ss += __shfl_xor_sync(0xffffffffu, ss, off);
    }
    if (lane == 0) {
        const float inv_n = 1.f / (float)(B_ * S_);
        float mean = s * inv_n;
        float var  = ss * inv_n - mean * mean;
        float a = gamma[ch] * rsqrtf(var + EPSV);
        g_bn_a[ch] = a;
        g_bn_b[ch] = beta[ch] - mean * a;
    }
}

// ---------------- kernel 2: precompute tf32-strided weights, v, w1t --------------
__global__ void setup_kernel(const float* __restrict__ w1,
                             const float* __restrict__ ws1,
                             const float* __restrict__ bs1,
                             const float* __restrict__ ws2,
                             const float* __restrict__ w2,
                             const float* __restrict__ W) {
    int idx = blockIdx.x * blockDim.x + threadIdx.x;
    if (idx < 4096) {
        int a = idx >> 6, b = idx & 63;
        float acc = 0.f;
        #pragma unroll 4
        for (int s = 0; s < 128; ++s)
            acc += ws1[s * 64 + a] * ws2[s * 64 + b];
        g_Ms [a * WST + b] = f2tf(acc);
        g_w2s[a * WST + b] = f2tf(w2[idx]);
        g_Wts[a * WST + b] = f2tf(W[b * 64 + a]);
    }
    if (idx < C_ * 64) g_w1t[idx] = w1[(idx & 63) * C_ + (idx >> 6)];
    if (idx < 64) {
        float acc = 0.f;
        #pragma unroll 4
        for (int s = 0; s < 128; ++s)
            acc += ws2[s * 64 + idx] * bs1[s];
        g_v[idx] = acc;
        #pragma unroll
        for (int e = 64; e < WST; ++e) {
            g_Ms [idx * WST + e] = 0;
            g_w2s[idx * WST + e] = 0;
            g_Wts[idx * WST + e] = 0;
        }
    }
    if (idx < 256) { g_bn_a[NCH + idx] = 0.f; g_bn_b[NCH + idx] = 0.f; }
}

// ---------------- smem layout (float offsets) ----------------------------------
#define OFF_W1T   0        // 256 (VH aliases after phase B)
#define OFF_B1    256
#define OFF_B2    320
#define OFF_V     384
#define OFF_SWB   448      // 64*68 = 4352: w2 only (LT aliases after C)
#define OFF_A1    4800     // 64*168 = 10752 : h1 -> G -> AGG(pixel-local)
#define OFF_A2    15552    // 64*168 = 10752 : XN -> H -> OUT stage
#define SMEM_FLOATS 26304
#define SMEM_BYTES (SMEM_FLOATS * 4)   // 105,216 B -> 2 blocks/SM
#define OFF_XN    OFF_A2
#define OFF_LT    OFF_SWB               // 8*532 = 4256 (w2 dead after C)
#define OFF_VH    OFF_W1T               // 160 (W1T dead after phase B)
#define SWB_U4    (64*WST/4)            // 1088 uint4

// ---- tf32 mma GEMM (10 warps): D = A(smem SWB) * B(offB); 2m x 4n --------------
template<int BIAS, int RELU, int CVT>
__device__ __forceinline__ void mma_phase(float* sm, int offB, int offD,
                                          int w, int lane) {
    u32* smu = (u32*)sm;
    const int r4 = lane >> 2, l4 = lane & 3;
    const int wm = (w >= 5) ? 1 : 0;
    const int wn = w - wm * 5;
    const int m0 = wm * 32;
    const int n0 = wn * 32;
    float d[2][4][4];
    #pragma unroll
    for (int mt = 0; mt < 2; ++mt) {
        float bz0 = 0.f, bz1 = 0.f;
        if (BIAS) {
            bz0 = sm[OFF_B2 + m0 + mt * 16 + r4];
            bz1 = sm[OFF_B2 + m0 + mt * 16 + 8 + r4];
        }
        #pragma unroll
        for (int nt = 0; nt < 4; ++nt) {
            d[mt][nt][0] = bz0; d[mt][nt][1] = bz0;
            d[mt][nt][2] = bz1; d[mt][nt][3] = bz1;
        }
    }
    #pragma unroll
    for (int k0 = 0; k0 < 64; k0 += 8) {
        u32 a[2][4];
        #pragma unroll
        for (int mt = 0; mt < 2; ++mt) {
            int base = OFF_SWB + (m0 + mt * 16 + r4) * WST + k0 + l4;
            a[mt][0] = smu[base];
            a[mt][1] = smu[base + 8 * WST];
            a[mt][2] = smu[base + 4];
            a[mt][3] = smu[base + 8 * WST + 4];
        }
        u32 b[4][2];
        #pragma unroll
        for (int nt = 0; nt < 4; ++nt) {
            int base = offB + (k0 + l4) * AST + n0 + nt * 8 + r4;
            b[nt][0] = smu[base];
            b[nt][1] = smu[base + 4 * AST];
        }
        #pragma unroll
        for (int nt = 0; nt < 4; ++nt)
            #pragma unroll
            for (int mt = 0; mt < 2; ++mt)
                mma_tf32(d[mt][nt], a[mt], b[nt]);
    }
    #pragma unroll
    for (int mt = 0; mt < 2; ++mt)
        #pragma unroll
        for (int nt = 0; nt < 4; ++nt) {
            int col = n0 + nt * 8 + l4 * 2;
            int row0 = m0 + mt * 16 + r4;
            float v0 = d[mt][nt][0], v1 = d[mt][nt][1];
            float v2 = d[mt][nt][2], v3 = d[mt][nt][3];
            if (RELU) {
                v0 = fmaxf(v0, 0.f); v1 = fmaxf(v1, 0.f);
                v2 = fmaxf(v2, 0.f); v3 = fmaxf(v3, 0.f);
            }
            if (CVT) {
                *(uint2*)&smu[offD + row0 * AST + col] =
                    make_uint2(f2tf(v0), f2tf(v1));
                *(uint2*)&smu[offD + (row0 + 8) * AST + col] =
                    make_uint2(f2tf(v2), f2tf(v3));
            } else {
                *(float2*)&sm[offD + row0 * AST + col] = make_float2(v0, v1);
                *(float2*)&sm[offD + (row0 + 8) * AST + col] = make_float2(v2, v3);
            }
        }
}

// ---- tf32 mma GEMM with A-fragments from GLOBAL (L1-resident weights) -----------
__device__ __forceinline__ void mma_phase_g(float* sm, const u32* __restrict__ gw,
                                            int offB, int offD, int w, int lane) {
    u32* smu = (u32*)sm;
    const int r4 = lane >> 2, l4 = lane & 3;
    const int wm = (w >= 5) ? 1 : 0;
    const int wn = w - wm * 5;
    const int m0 = wm * 32;
    const int n0 = wn * 32;
    float d[2][4][4];
    #pragma unroll
    for (int mt = 0; mt < 2; ++mt)
        #pragma unroll
        for (int nt = 0; nt < 4; ++nt)
            #pragma unroll
            for (int e = 0; e < 4; ++e) d[mt][nt][e] = 0.f;
    #pragma unroll
    for (int k0 = 0; k0 < 64; k0 += 8) {
        u32 a[2][4];
        #pragma unroll
        for (int mt = 0; mt < 2; ++mt) {
            const u32* base = gw + (m0 + mt * 16 + r4) * WST + k0 + l4;
            a[mt][0] = __ldg(base);
            a[mt][1] = __ldg(base + 8 * WST);
            a[mt][2] = __ldg(base + 4);
            a[mt][3] = __ldg(base + 8 * WST + 4);
        }
        u32 b[4][2];
        #pragma unroll
        for (int nt = 0; nt < 4; ++nt) {
            int base = offB + (k0 + l4) * AST + n0 + nt * 8 + r4;
            b[nt][0] = smu[base];
            b[nt][1] = smu[base + 4 * AST];
        }
        #pragma unroll
        for (int nt = 0; nt < 4; ++nt)
            #pragma unroll
            for (int mt = 0; mt < 2; ++mt)
                mma_tf32(d[mt][nt], a[mt], b[nt]);
    }
    #pragma unroll
    for (int mt = 0; mt < 2; ++mt)
        #pragma unroll
        for (int nt = 0; nt < 4; ++nt) {
            int col = n0 + nt * 8 + l4 * 2;
            int row0 = m0 + mt * 16 + r4;
            *(float2*)&sm[offD + row0 * AST + col] =
                make_float2(d[mt][nt][0], d[mt][nt][1]);
            *(float2*)&sm[offD + (row0 + 8) * AST + col] =
                make_float2(d[mt][nt][2], d[mt][nt][3]);
        }
}

__global__ __launch_bounds__(NTH, 2)
void geo_gcn_main_kernel(const float* __restrict__ x,
                         const float* __restrict__ b1g,
                         const float* __restrict__ b2g,
                         float* __restrict__ out) {
    extern __shared__ float sm[];
    u32* smu = (u32*)sm;
    const int tid = threadIdx.x;
    const int pix0 = blockIdx.x * PPB;
    const int w = tid >> 5, lane = tid & 31;
    const int r4 = lane >> 2, l4 = lane & 3;

    const int bb  = pix0 / 2560;
    const int ts0 = pix0 % 2560;

    // ---- prologue: SWB = w2s; w1t/biases/v; fused BN+XN; zero A2 pads ----
    for (int q = tid; q < SWB_U4; q += NTH)
        *(uint4*)&smu[OFF_SWB + q * 4] = *(const uint4*)&g_w2s[q * 4];
    if (tid < 64) {
        *(float4*)&sm[OFF_W1T + tid * 4] = *(const float4*)&g_w1t[tid * 4];
        sm[OFF_B1 + tid] = b1g[tid];
        sm[OFF_B2 + tid] = b2g[tid];
        sm[OFF_V  + tid] = g_v[tid];
    }
    if (tid < 76) {
        int ch = tid;
        int t0 = ts0 / 10, s0 = ts0 % 10;
        const float* xp = &x[((size_t)(bb * 76 + ch)) * 2560 + ts0];
        float4 v0 = *(const float4*)xp;
        float4 v1 = *(const float4*)(xp + 4);
        float a0 = g_bn_a[ch * 256 + t0];
        float bz0 = g_bn_b[ch * 256 + t0];
        float a1 = g_bn_a[ch * 256 + t0 + 1];
        float bz1 = g_bn_b[ch * 256 + t0 + 1];
        int c = ch / 19, j = ch % 19;
        float xv[8] = {v0.x, v0.y, v0.z, v0.w, v1.x, v1.y, v1.z, v1.w};
        #pragma unroll
        for (int p = 0; p < 8; ++p) {
            bool nx = (s0 + p >= 10);
            float val = xv[p] * (nx ? a1 : a0) + (nx ? bz1 : bz0);
            sm[OFF_XN + c * AST + p * 20 + j] = val;
        }
    } else if (tid >= 152 && tid < 160) {
        int pp = tid - 152;
        #pragma unroll
        for (int c = 0; c < C_; ++c)
            sm[OFF_XN + c * AST + pp * 20 + 19] = 0.f;
    } else if (tid >= 160 && tid < 288) {
        int u = tid - 160;
        int row = u >> 1, colb = 160 + (u & 1) * 4;
        *(float4*)&sm[OFF_A2 + row * AST + colb] = make_float4(0.f, 0.f, 0.f, 0.f);
    }
    __syncthreads();

    // ================= Phase B: h1 = relu(W1 xn + b1) -> A1 (tf32) ==========
    {
        const int dg = tid / 40, cg = tid % 40;
        const int d0 = dg * 8, col0 = cg * 4;
        u64 acc[8][2];
        #pragma unroll
        for (int i = 0; i < 8; ++i) {
            u64 bv = dup2(sm[OFF_B1 + d0 + i]);
            acc[i][0] = bv; acc[i][1] = bv;
        }
        #pragma unroll
        for (int k = 0; k < C_; ++k) {
            float4 w0 = *(const float4*)&sm[OFF_W1T + k * 64 + d0];
            float4 w1 = *(const float4*)&sm[OFF_W1T + k * 64 + d0 + 4];
            u64 a01, a23;
            lds_v2u64(&sm[OFF_XN + k * AST + col0], a01, a23);
            #pragma unroll
            for (int i = 0; i < 8; ++i) {
                u64 wd = dup2(i < 4 ? (&w0.x)[i] : (&w1.x)[i - 4]);
                fma2(acc[i][0], wd, a01);
                fma2(acc[i][1], wd, a23);
            }
        }
        #pragma unroll
        for (int i = 0; i < 8; ++i) {
            float v0, v1, v2, v3;
            upk2(acc[i][0], v0, v1); upk2(acc[i][1], v2, v3);
            *(uint4*)&smu[OFF_A1 + (d0 + i) * AST + col0] =
                make_uint4(f2tf(fmaxf(v0, 0.f)), f2tf(fmaxf(v1, 0.f)),
                           f2tf(fmaxf(v2, 0.f)), f2tf(fmaxf(v3, 0.f)));
        }
    }
    __syncthreads();

    // ================= Phase C: H = relu(w2 h1 + b2) -> A2 (tf32) ===========
    mma_phase<1, 1, 1>(sm, OFF_A1, OFF_A2, w, lane);
    __syncthreads();

    // ==== Phase D (8 warps): G = M H -> A1 (tf32), Ms from GLOBAL; w8,9: vh ====
    if (w < 8) {
        const int wm = w & 1, wn = w >> 1;
        const int m0 = wm * 32, n0 = wn * 40;
        float d[2][5][4];
        #pragma unroll
        for (int mt = 0; mt < 2; ++mt)
            #pragma unroll
            for (int nt = 0; nt < 5; ++nt)
                #pragma unroll
                for (int e = 0; e < 4; ++e) d[mt][nt][e] = 0.f;
        #pragma unroll
        for (int k0 = 0; k0 < 64; k0 += 8) {
            u32 a[2][4];
            #pragma unroll
            for (int mt = 0; mt < 2; ++mt) {
                const u32* base = g_Ms + (m0 + mt * 16 + r4) * WST + k0 + l4;
                a[mt][0] = __ldg(base);
                a[mt][1] = __ldg(base + 8 * WST);
                a[mt][2] = __ldg(base + 4);
                a[mt][3] = __ldg(base + 8 * WST + 4);
            }
            u32 b[5][2];
            #pragma unroll
            for (int nt = 0; nt < 5; ++nt) {
                int base = OFF_A2 + (k0 + l4) * AST + n0 + nt * 8 + r4;
                b[nt][0] = smu[base];
                b[nt][1] = smu[base + 4 * AST];
            }
            #pragma unroll
            for (int nt = 0; nt < 5; ++nt)
                #pragma unroll
                for (int mt = 0; mt < 2; ++mt)
                    mma_tf32(d[mt][nt], a[mt], b[nt]);
        }
        #pragma unroll
        for (int mt = 0; mt < 2; ++mt)
            #pragma unroll
            for (int nt = 0; nt < 5; ++nt) {
                int col = n0 + nt * 8 + l4 * 2;
                int row0 = m0 + mt * 16 + r4;
                *(uint2*)&smu[OFF_A1 + row0 * AST + col] =
                    make_uint2(f2tf(d[mt][nt][0]), f2tf(d[mt][nt][1]));
                *(uint2*)&smu[OFF_A1 + (row0 + 8) * AST + col] =
                    make_uint2(f2tf(d[mt][nt][2]), f2tf(d[mt][nt][3]));
            }
    } else {
        for (int u = (w - 8) * 32 + lane; u < 160; u += 64) {
            float a = 0.f;
            #pragma unroll 8
            for (int b = 0; b < 64; ++b)
                a += sm[OFF_V + b] * sm[OFF_A2 + b * AST + u];
            sm[OFF_VH + u] = a;
        }
    }
    __syncthreads();

    // ===== FUSED per-warp: logits -> softmax -> AGG (warp p owns pixel p) =====
    if (w < 8) {
        const int p20 = w * 20;
        float* ltp = &sm[OFF_LT + w * LTP];
        // ---- logits: L[j][k] = sum_a H[a][j] G[a][k] ----
        {
            float d[2][3][4];
            #pragma unroll
            for (int mt = 0; mt < 2; ++mt)
                #pragma unroll
                for (int nt = 0; nt < 3; ++nt)
                    #pragma unroll
                    for (int e = 0; e < 4; ++e) d[mt][nt][e] = 0.f;
            #pragma unroll
            for (int ks = 0; ks < 8; ++ks) {
                int kb = ks * 8 + l4;
                u32 a[2][4];
                a[0][0] = smu[OFF_A2 + kb * AST + p20 + r4];
                a[0][1] = smu[OFF_A2 + kb * AST + p20 + r4 + 8];
                a[0][2] = smu[OFF_A2 + (kb + 4) * AST + p20 + r4];
                a[0][3] = smu[OFF_A2 + (kb + 4) * AST + p20 + r4 + 8];
                int j2 = (16 + r4 < 19) ? 16 + r4 : 19;
                a[1][0] = smu[OFF_A2 + kb * AST + p20 + j2];
                a[1][1] = smu[OFF_A2 + kb * AST + p20 + 19];
                a[1][2] = smu[OFF_A2 + (kb + 4) * AST + p20 + j2];
                a[1][3] = smu[OFF_A2 + (kb + 4) * AST + p20 + 19];
                u32 b[3][2];
                #pragma unroll
                for (int nt = 0; nt < 3; ++nt) {
                    int kcol = nt * 8 + r4;
                    b[nt][0] = smu[OFF_A1 + kb * AST + p20 + kcol];
                    b[nt][1] = smu[OFF_A1 + (kb + 4) * AST + p20 + kcol];
                }
                #pragma unroll
                for (int mt = 0; mt < 2; ++mt)
                    #pragma unroll
                    for (int nt = 0; nt < 3; ++nt)
                        mma_tf32(d[mt][nt], a[mt], b[nt]);
            }
            #pragma unroll
            for (int mt = 0; mt < 2; ++mt)
                #pragma unroll
                for (int nt = 0; nt < 3; ++nt) {
                    int col = nt * 8 + l4 * 2;
                    int row = mt * 16 + r4;
                    if (row < J_) {
                        if (col < J_)     ltp[row * LTS + col]     = d[mt][nt][0];
                        if (col + 1 < J_) ltp[row * LTS + col + 1] = d[mt][nt][1];
                    }
                    if (row + 8 < J_) {
                        if (col < J_)     ltp[(row + 8) * LTS + col]     = d[mt][nt][2];
                        if (col + 1 < J_) ltp[(row + 8) * LTS + col + 1] = d[mt][nt][3];
                    }
                }
        }
        __syncwarp();
        // ---- softmax over k, lane j < 19 ----
        if (lane < J_) {
            int lb = lane * LTS;
            float l[J_];
            float mx = -1e30f;
            #pragma unroll
            for (int k = 0; k < J_; ++k) {
                l[k] = ltp[lb + k] + sm[OFF_VH + p20 + k];
                mx = fmaxf(mx, l[k]);
            }
            float sum = 0.f;
            #pragma unroll
            for (int k = 0; k < J_; ++k) { l[k] = __expf(l[k] - mx); sum += l[k]; }
            float inv = 1.f / sum;
            #pragma unroll
            for (int k = 0; k < J_; ++k)
                ((u32*)ltp)[lb + k] = f2tf(l[k] * inv);
            #pragma unroll
            for (int k = J_; k < LTS; ++k) ltp[lb + k] = 0.f;
        }
        __syncwarp();
        // ---- AGG: A[c][p20+j] = sum_k H[c][p20+k] att[j][k]  (4m x 3n x 3k) ----
        {
            float d[4][3][4];
            #pragma unroll
            for (int mt = 0; mt < 4; ++mt)
                #pragma unroll
                for (int nt = 0; nt < 3; ++nt)
                    #pragma unroll
                    for (int e = 0; e < 4; ++e) d[mt][nt][e] = 0.f;
            #pragma unroll
            for (int ks = 0; ks < 3; ++ks) {
                int kb = ks * 8 + l4;
                u32 a[4][4];
                #pragma unroll
                for (int mt = 0; mt < 4; ++mt) {
                    int c = mt * 16 + r4;
                    a[mt][0] = smu[OFF_A2 + c * AST + p20 + kb];
                    a[mt][1] = smu[OFF_A2 + (c + 8) * AST + p20 + kb];
                    a[mt][2] = smu[OFF_A2 + c * AST + p20 + kb + 4];
                    a[mt][3] = smu[OFF_A2 + (c + 8) * AST + p20 + kb + 4];
                }
                u32 b[3][2];
                #pragma unroll
                for (int nt = 0; nt < 3; ++nt) {
                    int jb = nt * 8 + r4; if (jb > 18) jb = 18;
                    b[nt][0] = ((u32*)ltp)[jb * LTS + kb];
                    b[nt][1] = ((u32*)ltp)[jb * LTS + kb + 4];
                }
                #pragma unroll
                for (int mt = 0; mt < 4; ++mt)
                    #pragma unroll
                    for (int nt = 0; nt < 3; ++nt)
                        mma_tf32(d[mt][nt], a[mt], b[nt]);
            }
            #pragma unroll
            for (int mt = 0; mt < 4; ++mt)
                #pragma unroll
                for (int nt = 0; nt < 3; ++nt) {
                    int c = mt * 16 + r4;
                    int j = nt * 8 + l4 * 2;
                    if (j < J_)     smu[OFF_A1 + c * AST + p20 + j]       = f2tf(d[mt][nt][0]);
                    if (j + 1 < J_) smu[OFF_A1 + c * AST + p20 + j + 1]   = f2tf(d[mt][nt][1]);
                    if (j < J_)     smu[OFF_A1 + (c + 8) * AST + p20 + j]     = f2tf(d[mt][nt][2]);
                    if (j + 1 < J_) smu[OFF_A1 + (c + 8) * AST + p20 + j + 1] = f2tf(d[mt][nt][3]);
                }
        }
    }
    __syncthreads();

    // ================= OUT: Wt * AGG -> stage into A2 (f32), Wts from GLOBAL ===
    mma_phase_g(sm, g_Wts, OFF_A1, OFF_A2, w, lane);
    __syncthreads();

    // ===== coalesced global store from A2[o][p*20+j] =====
    for (int v = tid; v < 64 * 38; v += NTH) {
        int o = v / 38, rr = v % 38;
        int j = rr >> 1, pb = (rr & 1) * 4;
        const float* src = &sm[OFF_A2 + o * AST + j];
        float4 t = make_float4(src[(pb + 0) * 20], src[(pb + 1) * 20],
                               src[(pb + 2) * 20], src[(pb + 3) * 20]);
        *(float4*)&out[((size_t)((bb * 64 + o) * J_ + j)) * 2560 + ts0 + pb] = t;
    }
}

// ------------------------------ launcher --------------------------------------
extern "C" void kernel_launch(void* const* d_in, const int* in_sizes, int n_in,
                              void* d_out, int out_size) {
    const float* x     = (const float*)d_in[0];
    const float* gamma = (const float*)d_in[1];
    const float* beta  = (const float*)d_in[2];
    const float* w1    = (const float*)d_in[3];
    const float* b1    = (const float*)d_in[4];
    const float* w2    = (const float*)d_in[5];
    const float* b2    = (const float*)d_in[6];
    const float* ws1   = (const float*)d_in[7];
    const float* bs1   = (const float*)d_in[8];
    const float* ws2   = (const float*)d_in[9];
    // d_in[10] = bs2 (softmax-invariant), d_in[11] = W
    const float* W     = (const float*)d_in[11];
    float* out = (float*)d_out;

    cudaFuncSetAttribute(geo_gcn_main_kernel,
                         cudaFuncAttributeMaxDynamicSharedMemorySize, SMEM_BYTES);

    bn_stats_kernel<<<NCH / 8, 256>>>(x, gamma, beta);
    setup_kernel<<<16, 256>>>(w1, ws1, bs1, ws2, w2, W);
    geo_gcn_main_kernel<<<NPIX / PPB, NTH, SMEM_BYTES>>>(x, b1, b2, out);
}

// round 16
// speedup vs baseline: 1.0149x; 1.0149x over previous
#include <cuda_runtime.h>
#include <cuda_bf16.h>
#include <math.h>

// Problem constants
#define B_  16
#define C_  4
#define J_  19
#define T_  256
#define S_  10
#define NCH (C_*J_*T_)          // 19456 BN channels
#define NPIX (B_*T_*S_)         // 40960 pixels
#define EPSV 1e-5f

#define PPB 8                   // pixels per block
#define AST 168                 // activation stride (8*l4+r4 conflict-free)
#define WST 68                  // weight stride (4*r4+l4 conflict-free)
#define NTH 320
#define LTS 28                  // LT row stride
#define LTP (J_*LTS)            // 532 per-pixel LT stride

typedef unsigned long long u64;
typedef unsigned int u32;

// ---- f32x2 packed helpers (scalar phases) --------------------------------------
__device__ __forceinline__ u64 dup2(float a) {
    u64 r; asm("mov.b64 %0, {%1, %1};" : "=l"(r) : "f"(a)); return r;
}
__device__ __forceinline__ void upk2(u64 v, float& lo, float& hi) {
    asm("mov.b64 {%0, %1}, %2;" : "=f"(lo), "=f"(hi) : "l"(v));
}
__device__ __forceinline__ void fma2(u64& d, u64 a, u64 b) {
    asm("fma.rn.f32x2 %0, %1, %2, %0;" : "+l"(d) : "l"(a), "l"(b));
}
__device__ __forceinline__ void lds_v2u64(const float* p, u64& lo, u64& hi) {
    unsigned a = (unsigned)__cvta_generic_to_shared(p);
    asm("ld.shared.v2.u64 {%0, %1}, [%2];" : "=l"(lo), "=l"(hi) : "r"(a));
}
// ---- tf32 helpers ---------------------------------------------------------------
__device__ __forceinline__ u32 f2tf(float f) {
    u32 u; asm("cvt.rna.tf32.f32 %0, %1;" : "=r"(u) : "f"(f)); return u;
}
__device__ __forceinline__ void mma_tf32(float d[4], const u32 a[4], const u32 b[2]) {
    asm volatile(
        "mma.sync.aligned.m16n8k8.row.col.f32.tf32.tf32.f32 "
        "{%0,%1,%2,%3}, {%4,%5,%6,%7}, {%8,%9}, {%0,%1,%2,%3};\n"
        : "+f"(d[0]), "+f"(d[1]), "+f"(d[2]), "+f"(d[3])
        : "r"(a[0]), "r"(a[1]), "r"(a[2]), "r"(a[3]), "r"(b[0]), "r"(b[1]));
}

// ---------------- device scratch ----------------------------------------------
__device__ float g_bn_a[NCH + 256];   // +pad so t+1 overread is safe
__device__ float g_bn_b[NCH + 256];
__device__ float g_w1t[C_*64];        // w1t[c][d] (fp32, phase B)
__device__ u32   g_w2s[64*WST];       // tf32, strided: [d*68 + k]
__device__ u32   g_Ms [64*WST];       // tf32 M[a][b] at [a*68 + b]
__device__ u32   g_Wts[64*WST];       // tf32 Wt[o][c] at [o*68 + c]
__device__ float g_v[64];

// ------ kernel 1: BN statistics + (blocks 0..15) weight setup -------------------
__global__ void prep_kernel(const float* __restrict__ x,
                            const float* __restrict__ gamma,
                            const float* __restrict__ beta,
                            const float* __restrict__ w1,
                            const float* __restrict__ ws1,
                            const float* __restrict__ bs1,
                            const float* __restrict__ ws2,
                            const float* __restrict__ w2,
                            const float* __restrict__ W) {
    // ---- BN stats: one warp per channel ----
    int ch = blockIdx.x * 8 + (threadIdx.x >> 5);
    int lane = threadIdx.x & 31;
    if (ch < NCH) {
        float s = 0.f, ss = 0.f;
        for (int e = lane; e < B_ * S_; e += 32) {
            int b = e / S_, si = e % S_;
            float v = x[(b * NCH + ch) * S_ + si];
            s += v; ss += v * v;
        }
        #pragma unroll
        for (int off = 16; off; off >>= 1) {
            s  += __shfl_xor_sync(0xffffffffu, s,  off);
            ss += __shfl_xor_sync(0xffffffffu, ss, off);
        }
        if (lane == 0) {
            const float inv_n = 1.f / (float)(B_ * S_);
            float mean = s * inv_n;
            float var  = ss * inv_n - mean * mean;
            float a = gamma[ch] * rsqrtf(var + EPSV);
            g_bn_a[ch] = a;
            g_bn_b[ch] = beta[ch] - mean * a;
        }
    }
    // ---- setup (blocks 0..15 only, idx 0..4095) ----
    if (blockIdx.x < 16) {
        int idx = blockIdx.x * 256 + threadIdx.x;
        {
            int a = idx >> 6, b = idx & 63;
            float acc = 0.f;
            #pragma unroll 4
            for (int s = 0; s < 128; ++s)
                acc += ws1[s * 64 + a] * ws2[s * 64 + b];
            g_Ms [a * WST + b] = f2tf(acc);
            g_w2s[a * WST + b] = f2tf(w2[idx]);
            g_Wts[a * WST + b] = f2tf(W[b * 64 + a]);
        }
        if (idx < C_ * 64) g_w1t[idx] = w1[(idx & 63) * C_ + (idx >> 6)];
        if (idx < 64) {
            float acc = 0.f;
            #pragma unroll 4
            for (int s = 0; s < 128; ++s)
                acc += ws2[s * 64 + idx] * bs1[s];
            g_v[idx] = acc;
            #pragma unroll
            for (int e = 64; e < WST; ++e) {
                g_Ms [idx * WST + e] = 0;
                g_w2s[idx * WST + e] = 0;
                g_Wts[idx * WST + e] = 0;
            }
        }
        if (idx < 256) { g_bn_a[NCH + idx] = 0.f; g_bn_b[NCH + idx] = 0.f; }
    }
}

// ---------------- smem layout (float offsets) ----------------------------------
#define OFF_W1T   0        // 256 (VH aliases after phase B)
#define OFF_B1    256
#define OFF_B2    320
#define OFF_V     384
#define OFF_SWB   448      // 64*68 = 4352, time-shared: w2 -> Ms -> LT -> Wts
#define OFF_A1    4800     // 64*168 = 10752 : h1 -> G -> AGG(pixel-local)
#define OFF_A2    15552    // 64*168 = 10752 : XN -> H -> OUT stage
#define SMEM_FLOATS 26304
#define SMEM_BYTES (SMEM_FLOATS * 4)   // 105,216 B -> 2 blocks/SM
#define OFF_XN    OFF_A2
#define OFF_LT    OFF_SWB               // 8*532 = 4256 (w2 dead after C)
#define OFF_VH    OFF_W1T               // 160 (W1T dead after phase B)
#define SWB_U4    (64*WST/4)            // 1088 uint4

// ---- tf32 mma GEMM (10 warps): D = A(smem SWB) * B(offB); 2m x 4n --------------
__device__ __forceinline__ void mma_phase10(float* sm, int offB, int offD,
                                            int w, int lane) {
    u32* smu = (u32*)sm;
    const int r4 = lane >> 2, l4 = lane & 3;
    const int wm = (w >= 5) ? 1 : 0;
    const int wn = w - wm * 5;
    const int m0 = wm * 32;
    const int n0 = wn * 32;
    float d[2][4][4];
    #pragma unroll
    for (int mt = 0; mt < 2; ++mt)
        #pragma unroll
        for (int nt = 0; nt < 4; ++nt)
            #pragma unroll
            for (int e = 0; e < 4; ++e) d[mt][nt][e] = 0.f;
    #pragma unroll
    for (int k0 = 0; k0 < 64; k0 += 8) {
        u32 a[2][4];
        #pragma unroll
        for (int mt = 0; mt < 2; ++mt) {
            int base = OFF_SWB + (m0 + mt * 16 + r4) * WST + k0 + l4;
            a[mt][0] = smu[base];
            a[mt][1] = smu[base + 8 * WST];
            a[mt][2] = smu[base + 4];
            a[mt][3] = smu[base + 8 * WST + 4];
        }
        u32 b[4][2];
        #pragma unroll
        for (int nt = 0; nt < 4; ++nt) {
            int base = offB + (k0 + l4) * AST + n0 + nt * 8 + r4;
            b[nt][0] = smu[base];
            b[nt][1] = smu[base + 4 * AST];
        }
        #pragma unroll
        for (int nt = 0; nt < 4; ++nt)
            #pragma unroll
            for (int mt = 0; mt < 2; ++mt)
                mma_tf32(d[mt][nt], a[mt], b[nt]);
    }
    #pragma unroll
    for (int mt = 0; mt < 2; ++mt)
        #pragma unroll
        for (int nt = 0; nt < 4; ++nt) {
            int col = n0 + nt * 8 + l4 * 2;
            int row0 = m0 + mt * 16 + r4;
            *(float2*)&sm[offD + row0 * AST + col] =
                make_float2(d[mt][nt][0], d[mt][nt][1]);
            *(float2*)&sm[offD + (row0 + 8) * AST + col] =
                make_float2(d[mt][nt][2], d[mt][nt][3]);
        }
}

__global__ __launch_bounds__(NTH, 2)
void geo_gcn_main_kernel(const float* __restrict__ x,
                         const float* __restrict__ b1g,
                         const float* __restrict__ b2g,
                         float* __restrict__ out) {
    extern __shared__ float sm[];
    u32* smu = (u32*)sm;
    const int tid = threadIdx.x;
    const int pix0 = blockIdx.x * PPB;
    const int w = tid >> 5, lane = tid & 31;
    const int r4 = lane >> 2, l4 = lane & 3;

    const int bb  = pix0 / 2560;
    const int ts0 = pix0 % 2560;

    // ---- prologue: SWB = w2s; w1t/biases/v; fused BN+XN; zero A2 pads ----
    for (int q = tid; q < SWB_U4; q += NTH)
        *(uint4*)&smu[OFF_SWB + q * 4] = *(const uint4*)&g_w2s[q * 4];
    if (tid < 64) {
        *(float4*)&sm[OFF_W1T + tid * 4] = *(const float4*)&g_w1t[tid * 4];
        sm[OFF_B1 + tid] = b1g[tid];
        sm[OFF_B2 + tid] = b2g[tid];
        sm[OFF_V  + tid] = g_v[tid];
    }
    if (tid < 76) {
        int ch = tid;
        int t0 = ts0 / 10, s0 = ts0 % 10;
        const float* xp = &x[((size_t)(bb * 76 + ch)) * 2560 + ts0];
        float4 v0 = *(const float4*)xp;
        float4 v1 = *(const float4*)(xp + 4);
        float a0 = g_bn_a[ch * 256 + t0];
        float bz0 = g_bn_b[ch * 256 + t0];
        float a1 = g_bn_a[ch * 256 + t0 + 1];
        float bz1 = g_bn_b[ch * 256 + t0 + 1];
        int c = ch / 19, j = ch % 19;
        float xv[8] = {v0.x, v0.y, v0.z, v0.w, v1.x, v1.y, v1.z, v1.w};
        #pragma unroll
        for (int p = 0; p < 8; ++p) {
            bool nx = (s0 + p >= 10);
            float val = xv[p] * (nx ? a1 : a0) + (nx ? bz1 : bz0);
            sm[OFF_XN + c * AST + p * 20 + j] = val;
        }
    } else if (tid >= 152 && tid < 160) {
        int pp = tid - 152;
        #pragma unroll
        for (int c = 0; c < C_; ++c)
            sm[OFF_XN + c * AST + pp * 20 + 19] = 0.f;
    } else if (tid >= 160 && tid < 288) {
        int u = tid - 160;
        int row = u >> 1, colb = 160 + (u & 1) * 4;
        *(float4*)&sm[OFF_A2 + row * AST + colb] = make_float4(0.f, 0.f, 0.f, 0.f);
    }
    __syncthreads();

    // ================= Phase B: h1 = relu(W1 xn + b1) -> A1 (tf32) ==========
    {
        const int dg = tid / 40, cg = tid % 40;
        const int d0 = dg * 8, col0 = cg * 4;
        u64 acc[8][2];
        #pragma unroll
        for (int i = 0; i < 8; ++i) {
            u64 bv = dup2(sm[OFF_B1 + d0 + i]);
            acc[i][0] = bv; acc[i][1] = bv;
        }
        #pragma unroll
        for (int k = 0; k < C_; ++k) {
            float4 w0 = *(const float4*)&sm[OFF_W1T + k * 64 + d0];
            float4 w1 = *(const float4*)&sm[OFF_W1T + k * 64 + d0 + 4];
            u64 a01, a23;
            lds_v2u64(&sm[OFF_XN + k * AST + col0], a01, a23);
            #pragma unroll
            for (int i = 0; i < 8; ++i) {
                u64 wd = dup2(i < 4 ? (&w0.x)[i] : (&w1.x)[i - 4]);
                fma2(acc[i][0], wd, a01);
                fma2(acc[i][1], wd, a23);
            }
        }
        #pragma unroll
        for (int i = 0; i < 8; ++i) {
            float v0, v1, v2, v3;
            upk2(acc[i][0], v0, v1); upk2(acc[i][1], v2, v3);
            *(uint4*)&smu[OFF_A1 + (d0 + i) * AST + col0] =
                make_uint4(f2tf(fmaxf(v0, 0.f)), f2tf(fmaxf(v1, 0.f)),
                           f2tf(fmaxf(v2, 0.f)), f2tf(fmaxf(v3, 0.f)));
        }
    }
    __syncthreads();

    // ===== Phase C (8 warps): H = relu(w2 h1 + b2) -> A2; w8,9 prefetch Ms =====
    uint4 pref[17];
    if (w < 8) {
        const int wm = w & 1, wn = w >> 1;
        const int m0 = wm * 32, n0 = wn * 40;
        float d[2][5][4];
        #pragma unroll
        for (int mt = 0; mt < 2; ++mt) {
            float bz0 = sm[OFF_B2 + m0 + mt * 16 + r4];
            float bz1 = sm[OFF_B2 + m0 + mt * 16 + 8 + r4];
            #pragma unroll
            for (int nt = 0; nt < 5; ++nt) {
                d[mt][nt][0] = bz0; d[mt][nt][1] = bz0;
                d[mt][nt][2] = bz1; d[mt][nt][3] = bz1;
            }
        }
        #pragma unroll
        for (int k0 = 0; k0 < 64; k0 += 8) {
            u32 a[2][4];
            #pragma unroll
            for (int mt = 0; mt < 2; ++mt) {
                int base = OFF_SWB + (m0 + mt * 16 + r4) * WST + k0 + l4;
                a[mt][0] = smu[base];
                a[mt][1] = smu[base + 8 * WST];
                a[mt][2] = smu[base + 4];
                a[mt][3] = smu[base + 8 * WST + 4];
            }
            u32 b[5][2];
            #pragma unroll
            for (int nt = 0; nt < 5; ++nt) {
                int base = OFF_A1 + (k0 + l4) * AST + n0 + nt * 8 + r4;
                b[nt][0] = smu[base];
                b[nt][1] = smu[base + 4 * AST];
            }
            #pragma unroll
            for (int nt = 0; nt < 5; ++nt)
                #pragma unroll
                for (int mt = 0; mt < 2; ++mt)
                    mma_tf32(d[mt][nt], a[mt], b[nt]);
        }
        #pragma unroll
        for (int mt = 0; mt < 2; ++mt)
            #pragma unroll
            for (int nt = 0; nt < 5; ++nt) {
                int col = n0 + nt * 8 + l4 * 2;
                int row0 = m0 + mt * 16 + r4;
                *(uint2*)&smu[OFF_A2 + row0 * AST + col] =
                    make_uint2(f2tf(fmaxf(d[mt][nt][0], 0.f)),
                               f2tf(fmaxf(d[mt][nt][1], 0.f)));
                *(uint2*)&smu[OFF_A2 + (row0 + 8) * AST + col] =
                    make_uint2(f2tf(fmaxf(d[mt][nt][2], 0.f)),
                               f2tf(fmaxf(d[mt][nt][3], 0.f)));
            }
    } else {
        int idx = tid - 256;   // 0..63
        #pragma unroll
        for (int i = 0; i < 17; ++i)
            pref[i] = *(const uint4*)&g_Ms[(idx + 64 * i) * 4];
    }
    __syncthreads();

    // ---- w8,9: commit Ms to SWB (w2 dead) ----
    if (w >= 8) {
        int idx = tid - 256;
        #pragma unroll
        for (int i = 0; i < 17; ++i)
            *(uint4*)&smu[OFF_SWB + (idx + 64 * i) * 4] = pref[i];
    }
    __syncthreads();

    // ========= Phase D (8 warps): G = M H -> A1 (tf32);  warps 8,9: vh ========
    if (w < 8) {
        const int wm = w & 1, wn = w >> 1;
        const int m0 = wm * 32, n0 = wn * 40;
        float d[2][5][4];
        #pragma unroll
        for (int mt = 0; mt < 2; ++mt)
            #pragma unroll
            for (int nt = 0; nt < 5; ++nt)
                #pragma unroll
                for (int e = 0; e < 4; ++e) d[mt][nt][e] = 0.f;
        #pragma unroll
        for (int k0 = 0; k0 < 64; k0 += 8) {
            u32 a[2][4];
            #pragma unroll
            for (int mt = 0; mt < 2; ++mt) {
                int base = OFF_SWB + (m0 + mt * 16 + r4) * WST + k0 + l4;
                a[mt][0] = smu[base];
                a[mt][1] = smu[base + 8 * WST];
                a[mt][2] = smu[base + 4];
                a[mt][3] = smu[base + 8 * WST + 4];
            }
            u32 b[5][2];
            #pragma unroll
            for (int nt = 0; nt < 5; ++nt) {
                int base = OFF_A2 + (k0 + l4) * AST + n0 + nt * 8 + r4;
                b[nt][0] = smu[base];
                b[nt][1] = smu[base + 4 * AST];
            }
            #pragma unroll
            for (int nt = 0; nt < 5; ++nt)
                #pragma unroll
                for (int mt = 0; mt < 2; ++mt)
                    mma_tf32(d[mt][nt], a[mt], b[nt]);
        }
        #pragma unroll
        for (int mt = 0; mt < 2; ++mt)
            #pragma unroll
            for (int nt = 0; nt < 5; ++nt) {
                int col = n0 + nt * 8 + l4 * 2;
                int row0 = m0 + mt * 16 + r4;
                *(uint2*)&smu[OFF_A1 + row0 * AST + col] =
                    make_uint2(f2tf(d[mt][nt][0]), f2tf(d[mt][nt][1]));
                *(uint2*)&smu[OFF_A1 + (row0 + 8) * AST + col] =
                    make_uint2(f2tf(d[mt][nt][2]), f2tf(d[mt][nt][3]));
            }
    } else {
        for (int u = (w - 8) * 32 + lane; u < 160; u += 64) {
            float a = 0.f;
            #pragma unroll 8
            for (int b = 0; b < 64; ++b)
                a += sm[OFF_V + b] * sm[OFF_A2 + b * AST + u];
            sm[OFF_VH + u] = a;
        }
    }
    __syncthreads();

    // ===== FUSED per-warp: logits -> softmax -> AGG; w8,9 prefetch Wts =====
    if (w < 8) {
        const int p20 = w * 20;
        float* ltp = &sm[OFF_LT + w * LTP];
        // ---- logits: L[j][k] = sum_a H[a][j] G[a][k] ----
        {
            float d[2][3][4];
            #pragma unroll
            for (int mt = 0; mt < 2; ++mt)
                #pragma unroll
                for (int nt = 0; nt < 3; ++nt)
                    #pragma unroll
                    for (int e = 0; e < 4; ++e) d[mt][nt][e] = 0.f;
            #pragma unroll
            for (int ks = 0; ks < 8; ++ks) {
                int kb = ks * 8 + l4;
                u32 a[2][4];
                a[0][0] = smu[OFF_A2 + kb * AST + p20 + r4];
                a[0][1] = smu[OFF_A2 + kb * AST + p20 + r4 + 8];
                a[0][2] = smu[OFF_A2 + (kb + 4) * AST + p20 + r4];
                a[0][3] = smu[OFF_A2 + (kb + 4) * AST + p20 + r4 + 8];
                int j2 = (16 + r4 < 19) ? 16 + r4 : 19;
                a[1][0] = smu[OFF_A2 + kb * AST + p20 + j2];
                a[1][1] = smu[OFF_A2 + kb * AST + p20 + 19];
                a[1][2] = smu[OFF_A2 + (kb + 4) * AST + p20 + j2];
                a[1][3] = smu[OFF_A2 + (kb + 4) * AST + p20 + 19];
                u32 b[3][2];
                #pragma unroll
                for (int nt = 0; nt < 3; ++nt) {
                    int kcol = nt * 8 + r4;
                    b[nt][0] = smu[OFF_A1 + kb * AST + p20 + kcol];
                    b[nt][1] = smu[OFF_A1 + (kb + 4) * AST + p20 + kcol];
                }
                #pragma unroll
                for (int mt = 0; mt < 2; ++mt)
                    #pragma unroll
                    for (int nt = 0; nt < 3; ++nt)
                        mma_tf32(d[mt][nt], a[mt], b[nt]);
            }
            #pragma unroll
            for (int mt = 0; mt < 2; ++mt)
                #pragma unroll
                for (int nt = 0; nt < 3; ++nt) {
                    int col = nt * 8 + l4 * 2;
                    int row = mt * 16 + r4;
                    if (row < J_) {
                        if (col < J_)     ltp[row * LTS + col]     = d[mt][nt][0];
                        if (col + 1 < J_) ltp[row * LTS + col + 1] = d[mt][nt][1];
                    }
                    if (row + 8 < J_) {
                        if (col < J_)     ltp[(row + 8) * LTS + col]     = d[mt][nt][2];
                        if (col + 1 < J_) ltp[(row + 8) * LTS + col + 1] = d[mt][nt][3];
                    }
                }
        }
        __syncwarp();
        // ---- softmax over k, lane j < 19 ----
        if (lane < J_) {
            int lb = lane * LTS;
            float l[J_];
            float mx = -1e30f;
            #pragma unroll
            for (int k = 0; k < J_; ++k) {
                l[k] = ltp[lb + k] + sm[OFF_VH + p20 + k];
                mx = fmaxf(mx, l[k]);
            }
            float sum = 0.f;
            #pragma unroll
            for (int k = 0; k < J_; ++k) { l[k] = __expf(l[k] - mx); sum += l[k]; }
            float inv = 1.f / sum;
            #pragma unroll
            for (int k = 0; k < J_; ++k)
                ((u32*)ltp)[lb + k] = f2tf(l[k] * inv);
            #pragma unroll
            for (int k = J_; k < LTS; ++k) ltp[lb + k] = 0.f;
        }
        __syncwarp();
        // ---- AGG: A[c][p20+j] = sum_k H[c][p20+k] att[j][k]  (4m x 3n x 3k) ----
        {
            float d[4][3][4];
            #pragma unroll
            for (int mt = 0; mt < 4; ++mt)
                #pragma unroll
                for (int nt = 0; nt < 3; ++nt)
                    #pragma unroll
                    for (int e = 0; e < 4; ++e) d[mt][nt][e] = 0.f;
            #pragma unroll
            for (int ks = 0; ks < 3; ++ks) {
                int kb = ks * 8 + l4;
                u32 a[4][4];
                #pragma unroll
                for (int mt = 0; mt < 4; ++mt) {
                    int c = mt * 16 + r4;
                    a[mt][0] = smu[OFF_A2 + c * AST + p20 + kb];
                    a[mt][1] = smu[OFF_A2 + (c + 8) * AST + p20 + kb];
                    a[mt][2] = smu[OFF_A2 + c * AST + p20 + kb + 4];
                    a[mt][3] = smu[OFF_A2 + (c + 8) * AST + p20 + kb + 4];
                }
                u32 b[3][2];
                #pragma unroll
                for (int nt = 0; nt < 3; ++nt) {
                    int jb = nt * 8 + r4; if (jb > 18) jb = 18;
                    b[nt][0] = ((u32*)ltp)[jb * LTS + kb];
                    b[nt][1] = ((u32*)ltp)[jb * LTS + kb + 4];
                }
                #pragma unroll
                for (int mt = 0; mt < 4; ++mt)
                    #pragma unroll
                    for (int nt = 0; nt < 3; ++nt)
                        mma_tf32(d[mt][nt], a[mt], b[nt]);
            }
            #pragma unroll
            for (int mt = 0; mt < 4; ++mt)
                #pragma unroll
                for (int nt = 0; nt < 3; ++nt) {
                    int c = mt * 16 + r4;
                    int j = nt * 8 + l4 * 2;
                    if (j < J_)     smu[OFF_A1 + c * AST + p20 + j]       = f2tf(d[mt][nt][0]);
                    if (j + 1 < J_) smu[OFF_A1 + c * AST + p20 + j + 1]   = f2tf(d[mt][nt][1]);
                    if (j < J_)     smu[OFF_A1 + (c + 8) * AST + p20 + j]     = f2tf(d[mt][nt][2]);
                    if (j + 1 < J_) smu[OFF_A1 + (c + 8) * AST + p20 + j + 1] = f2tf(d[mt][nt][3]);
                }
        }
    } else {
        int idx = tid - 256;   // prefetch Wts into regs
        #pragma unroll
        for (int i = 0; i < 17; ++i)
            pref[i] = *(const uint4*)&g_Wts[(idx + 64 * i) * 4];
    }
    __syncthreads();

    // ---- w8,9: commit Wts to SWB (LT dead) ----
    if (w >= 8) {
        int idx = tid - 256;
        #pragma unroll
        for (int i = 0; i < 17; ++i)
            *(uint4*)&smu[OFF_SWB + (idx + 64 * i) * 4] = pref[i];
    }
    __syncthreads();

    // ================= OUT: Wt * AGG -> stage into A2 (f32) ==================
    mma_phase10(sm, OFF_A1, OFF_A2, w, lane);
    __syncthreads();

    // ===== coalesced global store from A2[o][p*20+j] =====
    for (int v = tid; v < 64 * 38; v += NTH) {
        int o = v / 38, rr = v % 38;
        int j = rr >> 1, pb = (rr & 1) * 4;
        const float* src = &sm[OFF_A2 + o * AST + j];
        float4 t = make_float4(src[(pb + 0) * 20], src[(pb + 1) * 20],
                               src[(pb + 2) * 20], src[(pb + 3) * 20]);
        *(float4*)&out[((size_t)((bb * 64 + o) * J_ + j)) * 2560 + ts0 + pb] = t;
    }
}

// ------------------------------ launcher --------------------------------------
extern "C" void kernel_launch(void* const* d_in, const int* in_sizes, int n_in,
                              void* d_out, int out_size) {
    const float* x     = (const float*)d_in[0];
    const float* gamma = (const float*)d_in[1];
    const float* beta  = (const float*)d_in[2];
    const float* w1    = (const float*)d_in[3];
    const float* b1    = (const float*)d_in[4];
    const float* w2    = (const float*)d_in[5];
    const float* b2    = (const float*)d_in[6];
    const float* ws1   = (const float*)d_in[7];
    const float* bs1   = (const float*)d_in[8];
    const float* ws2   = (const float*)d_in[9];
    // d_in[10] = bs2 (softmax-invariant), d_in[11] = W
    const float* W     = (const float*)d_in[11];
    float* out = (float*)d_out;

    cudaFuncSetAttribute(geo_gcn_main_kernel,
                         cudaFuncAttributeMaxDynamicSharedMemorySize, SMEM_BYTES);

    prep_kernel<<<NCH / 8, 256>>>(x, gamma, beta, w1, ws1, bs1, ws2, w2, W);
    geo_gcn_main_kernel<<<NPIX / PPB, NTH, SMEM_BYTES>>>(x, b1, b2, out);
}